// round 1
// baseline (speedup 1.0000x reference)
#include <cuda_runtime.h>
#include <cstdint>

#define BATCH 8
#define SEQ   2048
#define DIM   1024
#define NST   256
#define HID   512
#define NEXP  8
#define NTOK  (BATCH*SEQ)   // 16384

// ---------------- device scratch (static, allocation-free) ----------------
__device__ float g_u [NTOK*NST];   // in_proj output
__device__ float g_sh[NTOK*HID];   // silu(selector_in)
__device__ float g_a [NTOK*NST];   // sigmoid gate a
__device__ float g_bu[NTOK*NST];   // tanh(b)*u
__device__ float g_c [NTOK*NST];   // tanh gate c
__device__ float g_sk[NTOK*NST];   // skip = d*sigmoid(dg)*u
__device__ float g_y [NTOK*NST];   // scan output
__device__ int   g_routes[NTOK];
__device__ int   g_lists[NEXP*NTOK];
__device__ int   g_counts[NEXP];

__device__ __forceinline__ float sigmoidf_(float x){ return 1.f/(1.f+__expf(-x)); }

// ---------------- routing ----------------
__global__ void zero_counts_kernel(){
    if (threadIdx.x < NEXP) g_counts[threadIdx.x] = 0;
}

__global__ void route_kernel(const int* __restrict__ token_ids){
    int t = blockIdx.x*blockDim.x + threadIdx.x;
    if (t >= NTOK) return;
    unsigned x = (unsigned)token_ids[t];
    x ^= x >> 16;
    x *= 2246822507u;
    x ^= x >> 13;
    x *= 3266489909u;
    x ^= x >> 16;
    int e = (int)(x & (NEXP-1));
    g_routes[t] = e;
    int pos = atomicAdd(&g_counts[e], 1);
    g_lists[e*NTOK + pos] = t;
}

// ---------------- grouped gather-GEMM: C = A_gather · W[e]^T -------------
// A rows gathered via per-expert token list; W row-major (nout, K).
// MODE: 0 = store u, 1 = silu->sh, 2 = gates epilogue, 3 = out projection
// ASRC: 0 = A param, 1 = g_sh, 2 = g_y
template<int MODE, int ASRC>
__global__ void __launch_bounds__(256)
gemm_gather(const float* __restrict__ Aparam, const float* __restrict__ Wt,
            const float* __restrict__ dparam, float* __restrict__ outp,
            int lda, int K, int nout)
{
    const int e   = blockIdx.z;
    const int cnt = g_counts[e];
    const int m0  = blockIdx.x * 128;
    if (m0 >= cnt) return;
    const int n0  = blockIdx.y * 128;
    const int* __restrict__ list = g_lists + e*NTOK;
    const float* __restrict__ A  = (ASRC==0) ? Aparam : (ASRC==1 ? g_sh : g_y);
    const float* __restrict__ W  = Wt + (size_t)e * nout * K;

    __shared__ float As[8][128];
    __shared__ float Bs[8][128];

    const int tid  = threadIdx.x;
    const int lrow = tid >> 1;
    const int lseg = (tid & 1) * 4;

    const int  mr   = m0 + lrow;
    const bool aval = (mr < cnt);
    const int  tokA = list[aval ? mr : (cnt-1)];
    const float* Aptr = A + (size_t)tokA * lda + lseg;
    const float* Wptr = W + (size_t)(n0 + lrow) * K + lseg;

    float acc[8][8];
    #pragma unroll
    for (int i=0;i<8;i++)
        #pragma unroll
        for (int j=0;j<8;j++) acc[i][j] = 0.f;

    const int trow = tid >> 4, tcol = tid & 15;
    const int mBase = trow*8, nBase = tcol*8;

    for (int k0 = 0; k0 < K; k0 += 8){
        float4 av = aval ? *(const float4*)(Aptr + k0) : make_float4(0.f,0.f,0.f,0.f);
        float4 bv = *(const float4*)(Wptr + k0);
        __syncthreads();
        As[lseg+0][lrow]=av.x; As[lseg+1][lrow]=av.y;
        As[lseg+2][lrow]=av.z; As[lseg+3][lrow]=av.w;
        Bs[lseg+0][lrow]=bv.x; Bs[lseg+1][lrow]=bv.y;
        Bs[lseg+2][lrow]=bv.z; Bs[lseg+3][lrow]=bv.w;
        __syncthreads();
        #pragma unroll
        for (int kk=0; kk<8; kk++){
            float af[8], bf[8];
            #pragma unroll
            for (int i=0;i<8;i++) af[i] = As[kk][mBase+i];
            #pragma unroll
            for (int j=0;j<8;j++) bf[j] = Bs[kk][nBase+j];
            #pragma unroll
            for (int i=0;i<8;i++)
                #pragma unroll
                for (int j=0;j<8;j++) acc[i][j] = fmaf(af[i], bf[j], acc[i][j]);
        }
    }

    #pragma unroll
    for (int i=0;i<8;i++){
        int m = m0 + mBase + i;
        if (m >= cnt) continue;
        int tok = list[m];
        #pragma unroll
        for (int j=0;j<8;j++){
            int col = n0 + nBase + j;
            float v = acc[i][j];
            if (MODE == 0){
                g_u[(size_t)tok*NST + col] = v;
            } else if (MODE == 1){
                g_sh[(size_t)tok*HID + col] = v * sigmoidf_(v);
            } else if (MODE == 2){
                size_t base = (size_t)tok * NST;
                if      (col < 256) g_a [base + col      ] = sigmoidf_(v);
                else if (col < 512) g_bu[base + col - 256] = tanhf(v) * g_u[base + col - 256];
                else if (col < 768) g_c [base + col - 512] = tanhf(v);
                else                g_sk[base + col - 768] = sigmoidf_(v) * dparam[e*NST + col - 768]
                                                             * g_u[base + col - 768];
            } else {
                outp[(size_t)tok*DIM + col] = v;
            }
        }
    }
}

// ---------------- sequential scan per (batch, expert) ----------------
// Block (b, e), 256 threads = one per state dim n. Compacts the ordered
// list of tokens routed to e, then walks the linear recurrence with a
// 1-step software prefetch.
__global__ void __launch_bounds__(256)
scan_kernel()
{
    const int b   = blockIdx.x;
    const int e   = blockIdx.y;
    const int tid = threadIdx.x;

    __shared__ int s_list[SEQ];
    __shared__ int s_wcnt[8];

    int count = 0;
    for (int base = 0; base < SEQ; base += 256){
        int t = base + tid;
        int r = g_routes[b*SEQ + t];
        bool act = (r == e);
        unsigned m = __ballot_sync(0xffffffffu, act);
        int wid = tid >> 5, lane = tid & 31;
        if (lane == 0) s_wcnt[wid] = __popc(m);
        __syncthreads();
        int woff = 0, tot = 0;
        #pragma unroll
        for (int w=0; w<8; w++){
            int c = s_wcnt[w];
            if (w < wid) woff += c;
            tot += c;
        }
        if (act) s_list[count + woff + __popc(m & ((1u<<lane)-1u))] = t;
        count += tot;
        __syncthreads();
    }

    float h = 0.f;
    if (count > 0){
        int t = s_list[0];
        size_t idx = ((size_t)b*SEQ + t)*NST + tid;
        float a = g_a[idx], bu = g_bu[idx], c = g_c[idx], sk = g_sk[idx];
        for (int i = 0; i < count; i++){
            float a2 = 0.f, bu2 = 0.f, c2 = 0.f, sk2 = 0.f;
            size_t idx2 = idx;
            if (i + 1 < count){
                int t2 = s_list[i+1];
                idx2 = ((size_t)b*SEQ + t2)*NST + tid;
                a2 = g_a[idx2]; bu2 = g_bu[idx2]; c2 = g_c[idx2]; sk2 = g_sk[idx2];
            }
            h = fmaf(a, h, bu);
            g_y[idx] = fmaf(c, h, sk);
            a = a2; bu = bu2; c = c2; sk = sk2; idx = idx2;
        }
    }
}

// ---------------- launch ----------------
extern "C" void kernel_launch(void* const* d_in, const int* in_sizes, int n_in,
                              void* d_out, int out_size)
{
    const float* x     = (const float*)d_in[0];
    const int*   tok   = (const int*)  d_in[1];
    const float* Win   = (const float*)d_in[2];
    const float* Wsin  = (const float*)d_in[3];
    const float* Wsout = (const float*)d_in[4];
    const float* Wout  = (const float*)d_in[5];
    const float* dpar  = (const float*)d_in[6];
    float* outp = (float*)d_out;
    (void)in_sizes; (void)n_in; (void)out_size;

    zero_counts_kernel<<<1, 32>>>();
    route_kernel<<<NTOK/256, 256>>>(tok);

    dim3 blk(256);
    // u = x · Win^T        (K=1024, nout=256)
    gemm_gather<0,0><<<dim3(128, 2, NEXP), blk>>>(x,      Win,   nullptr, nullptr, DIM, DIM, NST);
    // sh = silu(x · Wsin^T) (K=1024, nout=512)
    gemm_gather<1,0><<<dim3(128, 4, NEXP), blk>>>(x,      Wsin,  nullptr, nullptr, DIM, DIM, HID);
    // sel = sh · Wsout^T -> gates (K=512, nout=1024)
    gemm_gather<2,1><<<dim3(128, 8, NEXP), blk>>>(nullptr, Wsout, dpar,   nullptr, HID, HID, 4*NST);
    // recurrence
    scan_kernel<<<dim3(BATCH, NEXP), 256>>>();
    // out = y · Wout^T     (K=256, nout=1024)
    gemm_gather<3,2><<<dim3(128, 8, NEXP), blk>>>(nullptr, Wout,  nullptr, outp,   NST, NST, DIM);
}

// round 3
// speedup vs baseline: 2.2442x; 2.2442x over previous
#include <cuda_runtime.h>
#include <cuda_bf16.h>
#include <cstdint>

#define BATCH 8
#define SEQ   2048
#define DIM   1024
#define NST   256
#define HID   512
#define NEXP  8
#define NTOK  (BATCH*SEQ)   // 16384

// ---------------- device scratch (static, allocation-free) ----------------
__device__ float g_u [NTOK*NST];
__device__ float g_sh[NTOK*HID];
__device__ float g_a [NTOK*NST];
__device__ float g_bu[NTOK*NST];
__device__ float g_c [NTOK*NST];
__device__ float g_sk[NTOK*NST];
__device__ float g_y [NTOK*NST];
__device__ int   g_routes[NTOK];
__device__ int   g_lists[NEXP*NTOK];
__device__ int   g_counts[NEXP];

__device__ __forceinline__ float sigmoidf_(float x){ return 1.f/(1.f+__expf(-x)); }

__device__ __forceinline__ uint32_t smem_u32(const void* p){
    uint32_t a;
    asm("{ .reg .u64 t; cvta.to.shared.u64 t, %1; cvt.u32.u64 %0, t; }" : "=r"(a) : "l"(p));
    return a;
}
__device__ __forceinline__ void ldsm_x4(uint32_t* r, uint32_t addr){
    asm volatile("ldmatrix.sync.aligned.m8n8.x4.shared.b16 {%0,%1,%2,%3}, [%4];"
        : "=r"(r[0]),"=r"(r[1]),"=r"(r[2]),"=r"(r[3]) : "r"(addr));
}
__device__ __forceinline__ void mma16816(float* d, const uint32_t* a, uint32_t b0, uint32_t b1){
    asm volatile("mma.sync.aligned.m16n8k16.row.col.f32.bf16.bf16.f32 "
        "{%0,%1,%2,%3}, {%4,%5,%6,%7}, {%8,%9}, {%0,%1,%2,%3};"
        : "+f"(d[0]),"+f"(d[1]),"+f"(d[2]),"+f"(d[3])
        : "r"(a[0]),"r"(a[1]),"r"(a[2]),"r"(a[3]), "r"(b0),"r"(b1));
}

// split fp32x4 -> bf16 hi (uint2) + bf16 lo residual (uint2)
__device__ __forceinline__ void cvt4(float4 v, uint2& hi, uint2& lo){
    __nv_bfloat162 h0 = __floats2bfloat162_rn(v.x, v.y);
    __nv_bfloat162 h1 = __floats2bfloat162_rn(v.z, v.w);
    float r0 = v.x - __bfloat162float(__low2bfloat16 (h0));
    float r1 = v.y - __bfloat162float(__high2bfloat16(h0));
    float r2 = v.z - __bfloat162float(__low2bfloat16 (h1));
    float r3 = v.w - __bfloat162float(__high2bfloat16(h1));
    __nv_bfloat162 l0 = __floats2bfloat162_rn(r0, r1);
    __nv_bfloat162 l1 = __floats2bfloat162_rn(r2, r3);
    hi = make_uint2(*reinterpret_cast<uint32_t*>(&h0), *reinterpret_cast<uint32_t*>(&h1));
    lo = make_uint2(*reinterpret_cast<uint32_t*>(&l0), *reinterpret_cast<uint32_t*>(&l1));
}

// ---------------- routing ----------------
__global__ void zero_counts_kernel(){
    if (threadIdx.x < NEXP) g_counts[threadIdx.x] = 0;
}
__global__ void route_kernel(const int* __restrict__ token_ids){
    int t = blockIdx.x*blockDim.x + threadIdx.x;
    if (t >= NTOK) return;
    unsigned x = (unsigned)token_ids[t];
    x ^= x >> 16; x *= 2246822507u;
    x ^= x >> 13; x *= 3266489909u;
    x ^= x >> 16;
    int e = (int)(x & (NEXP-1));
    g_routes[t] = e;
    int pos = atomicAdd(&g_counts[e], 1);
    g_lists[e*NTOK + pos] = t;
}

// ---------------- grouped gather-GEMM (mma.sync bf16x3) -------------------
// C = A_gather . W[e]^T ; A rows gathered per expert; W row-major (nout,K)
// MODE: 0 u, 1 silu->sh, 2 gates, 3 out proj.   ASRC: 0 param, 1 g_sh, 2 g_y
// smem tiles: 128 rows x 32 bf16, padded row stride 40 bf16 (80B) -> conflict-free ldmatrix
#define SSTRIDE 80
#define STILE   (128*SSTRIDE)   // 10240

template<int MODE, int ASRC>
__global__ void __launch_bounds__(256)
gemm_mma(const float* __restrict__ Aparam, const float* __restrict__ Wt,
         const float* __restrict__ dparam, float* __restrict__ outp,
         int lda, int K, int nout)
{
    const int e   = blockIdx.z;
    const int cnt = g_counts[e];
    const int m0  = blockIdx.x * 128;
    if (m0 >= cnt) return;
    const int n0  = blockIdx.y * 128;
    const int* __restrict__ list = g_lists + e*NTOK;
    const float* __restrict__ A  = (ASRC==0) ? Aparam : (ASRC==1 ? g_sh : g_y);
    const float* __restrict__ W  = Wt + (size_t)e * nout * K;

    __shared__ __align__(16) char sm[4*STILE];   // Ah | Al | Bh | Bl
    __shared__ int s_tok[128];

    const int tid  = threadIdx.x;
    const int wid  = tid >> 5;
    const int lane = tid & 31;

    if (tid < 128){
        int m = m0 + tid;
        s_tok[tid] = list[m < cnt ? m : (cnt-1)];
    }
    __syncthreads();

    // ---- loader addressing: thread covers rows lrow+32*it, k seg (tid&7)*4
    const int lrow = tid >> 3;
    const int lk   = (tid & 7) * 4;
    const float* aptr[4];
    const float* wptr[4];
    #pragma unroll
    for (int it = 0; it < 4; it++){
        aptr[it] = A + (size_t)s_tok[lrow + it*32]*lda + lk;
        wptr[it] = W + (size_t)(n0 + lrow + it*32)*K + lk;
    }
    const int soff = lrow*SSTRIDE + lk*2;   // byte offset within tile (rows +32*it below)

    const uint32_t sb = smem_u32(sm);
    // ---- ldmatrix per-lane addresses
    const int wm = wid & 1, wn = wid >> 1;
    const uint32_t a_base = sb + (uint32_t)((wm*64 + (lane & 15))*SSTRIDE + (lane >> 4)*16);
    const uint32_t b_base = sb + 2*STILE +
        (uint32_t)((wn*32 + (lane >> 4)*8 + (lane & 7))*SSTRIDE + ((lane >> 3) & 1)*16);

    float acc[4][4][4];
    #pragma unroll
    for (int mi=0;mi<4;mi++)
        #pragma unroll
        for (int ni=0;ni<4;ni++)
            #pragma unroll
            for (int q=0;q<4;q++) acc[mi][ni][q]=0.f;

    const int NC = K >> 5;   // 32-wide chunks
    float4 pa[4], pb[4];
    #pragma unroll
    for (int it = 0; it < 4; it++){ pa[it] = *(const float4*)aptr[it]; pb[it] = *(const float4*)wptr[it]; }

    for (int c = 0; c < NC; c++){
        __syncthreads();   // previous compute finished with smem
        #pragma unroll
        for (int it = 0; it < 4; it++){
            uint2 hi, lo;
            int off = soff + it*32*SSTRIDE;
            cvt4(pa[it], hi, lo);
            *(uint2*)(sm + off)          = hi;
            *(uint2*)(sm + STILE + off)  = lo;
            cvt4(pb[it], hi, lo);
            *(uint2*)(sm + 2*STILE + off)= hi;
            *(uint2*)(sm + 3*STILE + off)= lo;
        }
        __syncthreads();
        if (c + 1 < NC){
            const int k1 = (c + 1) << 5;
            #pragma unroll
            for (int it = 0; it < 4; it++){
                pa[it] = *(const float4*)(aptr[it] + k1);
                pb[it] = *(const float4*)(wptr[it] + k1);
            }
        }
        #pragma unroll
        for (int ks = 0; ks < 2; ks++){
            uint32_t ah[4][4], al[4][4], bh[2][4], bl[2][4];
            #pragma unroll
            for (int mi = 0; mi < 4; mi++){
                uint32_t ad = a_base + mi*16*SSTRIDE + ks*32;
                ldsm_x4(ah[mi], ad);
                ldsm_x4(al[mi], ad + STILE);
            }
            #pragma unroll
            for (int np = 0; np < 2; np++){
                uint32_t bd = b_base + np*16*SSTRIDE + ks*32;
                ldsm_x4(bh[np], bd);
                ldsm_x4(bl[np], bd + STILE);
            }
            #pragma unroll
            for (int mi = 0; mi < 4; mi++)
                #pragma unroll
                for (int ni = 0; ni < 4; ni++){
                    const int np = ni >> 1, h = (ni & 1)*2;
                    mma16816(acc[mi][ni], ah[mi], bh[np][h], bh[np][h+1]);
                    mma16816(acc[mi][ni], ah[mi], bl[np][h], bl[np][h+1]);
                    mma16816(acc[mi][ni], al[mi], bh[np][h], bh[np][h+1]);
                }
        }
    }

    // ---- epilogue: c-frag rows t/4 (+8), cols 2*(t%4) (+1)
    const int sec = (MODE == 2) ? (n0 >> 8) : 0;
    #pragma unroll
    for (int mi = 0; mi < 4; mi++){
        const int rt0 = wm*64 + mi*16 + (lane >> 2);
        #pragma unroll
        for (int hf = 0; hf < 2; hf++){
            const int rt = rt0 + hf*8;
            const int m  = m0 + rt;
            if (m >= cnt) continue;
            const int tok = s_tok[rt];
            #pragma unroll
            for (int ni = 0; ni < 4; ni++){
                float v0 = acc[mi][ni][hf*2], v1 = acc[mi][ni][hf*2+1];
                const int col = n0 + wn*32 + (ni>>1)*16 + (ni&1)*8 + (lane&3)*2;
                if (MODE == 0){
                    *(float2*)(g_u + (size_t)tok*NST + col) = make_float2(v0, v1);
                } else if (MODE == 1){
                    *(float2*)(g_sh + (size_t)tok*HID + col) =
                        make_float2(v0*sigmoidf_(v0), v1*sigmoidf_(v1));
                } else if (MODE == 2){
                    const int off = col & 255;
                    const size_t base = (size_t)tok*NST + off;
                    if (sec == 0){
                        *(float2*)(g_a + base) = make_float2(sigmoidf_(v0), sigmoidf_(v1));
                    } else if (sec == 1){
                        float2 u2 = *(const float2*)(g_u + base);
                        *(float2*)(g_bu + base) = make_float2(tanhf(v0)*u2.x, tanhf(v1)*u2.y);
                    } else if (sec == 2){
                        *(float2*)(g_c + base) = make_float2(tanhf(v0), tanhf(v1));
                    } else {
                        float2 u2 = *(const float2*)(g_u + base);
                        float2 d2 = *(const float2*)(dparam + e*NST + off);
                        *(float2*)(g_sk + base) =
                            make_float2(sigmoidf_(v0)*d2.x*u2.x, sigmoidf_(v1)*d2.y*u2.y);
                    }
                } else {
                    *(float2*)(outp + (size_t)tok*DIM + col) = make_float2(v0, v1);
                }
            }
        }
    }
}

// ---------------- sequential scan per (batch, expert) ----------------
__global__ void __launch_bounds__(256)
scan_kernel()
{
    const int b   = blockIdx.x;
    const int e   = blockIdx.y;
    const int tid = threadIdx.x;

    __shared__ int s_list[SEQ];
    __shared__ int s_wcnt[8];

    int count = 0;
    for (int base = 0; base < SEQ; base += 256){
        int t = base + tid;
        int r = g_routes[b*SEQ + t];
        bool act = (r == e);
        unsigned m = __ballot_sync(0xffffffffu, act);
        int wid = tid >> 5, lane = tid & 31;
        if (lane == 0) s_wcnt[wid] = __popc(m);
        __syncthreads();
        int woff = 0, tot = 0;
        #pragma unroll
        for (int w = 0; w < 8; w++){
            int c = s_wcnt[w];
            if (w < wid) woff += c;
            tot += c;
        }
        if (act) s_list[count + woff + __popc(m & ((1u<<lane)-1u))] = t;
        count += tot;
        __syncthreads();
    }

    float h = 0.f;
    if (count > 0){
        int t = s_list[0];
        size_t idx = ((size_t)b*SEQ + t)*NST + tid;
        float a = g_a[idx], bu = g_bu[idx], c = g_c[idx], sk = g_sk[idx];
        for (int i = 0; i < count; i++){
            float a2 = 0.f, bu2 = 0.f, c2 = 0.f, sk2 = 0.f;
            size_t idx2 = idx;
            if (i + 1 < count){
                int t2 = s_list[i+1];
                idx2 = ((size_t)b*SEQ + t2)*NST + tid;
                a2 = g_a[idx2]; bu2 = g_bu[idx2]; c2 = g_c[idx2]; sk2 = g_sk[idx2];
            }
            h = fmaf(a, h, bu);
            g_y[idx] = fmaf(c, h, sk);
            a = a2; bu = bu2; c = c2; sk = sk2; idx = idx2;
        }
    }
}

// ---------------- launch ----------------
extern "C" void kernel_launch(void* const* d_in, const int* in_sizes, int n_in,
                              void* d_out, int out_size)
{
    const float* x     = (const float*)d_in[0];
    const int*   tok   = (const int*)  d_in[1];
    const float* Win   = (const float*)d_in[2];
    const float* Wsin  = (const float*)d_in[3];
    const float* Wsout = (const float*)d_in[4];
    const float* Wout  = (const float*)d_in[5];
    const float* dpar  = (const float*)d_in[6];
    float* outp = (float*)d_out;
    (void)in_sizes; (void)n_in; (void)out_size;

    zero_counts_kernel<<<1, 32>>>();
    route_kernel<<<NTOK/256, 256>>>(tok);

    dim3 blk(256);
    // u = x . Win^T         (K=1024, nout=256)
    gemm_mma<0,0><<<dim3(128, 2, NEXP), blk>>>(x,       Win,   nullptr, nullptr, DIM, DIM, NST);
    // sh = silu(x . Wsin^T) (K=1024, nout=512)
    gemm_mma<1,0><<<dim3(128, 4, NEXP), blk>>>(x,       Wsin,  nullptr, nullptr, DIM, DIM, HID);
    // sel = sh . Wsout^T -> gates (K=512, nout=1024)
    gemm_mma<2,1><<<dim3(128, 8, NEXP), blk>>>(nullptr, Wsout, dpar,    nullptr, HID, HID, 4*NST);
    // recurrence
    scan_kernel<<<dim3(BATCH, NEXP), 256>>>();
    // out = y . Wout^T      (K=256, nout=1024)
    gemm_mma<3,2><<<dim3(128, 8, NEXP), blk>>>(nullptr, Wout,  nullptr, outp,    NST, NST, DIM);
}